// round 12
// baseline (speedup 1.0000x reference)
#include <cuda_runtime.h>

#define HW      256
#define NB      8
#define CH      64
#define HWHW    65536
#define THREADS 512
#define RB      4                        // rows per block

// dynamic smem: part[6][2][4][64] f4 (48K) + nrm[6][2][256] f (12K) + f1/f2[1024] (8K)
#define PART_F4   (6 * 2 * 4 * 64)       // 3072 float4
#define NRM_F     (6 * 2 * HW)           // 3072 float
#define SMEM_TOTAL (PART_F4 * 16 + NRM_F * 4 + 2 * RB * HW * 4)   // 69632

extern __shared__ char smem[];

__device__ __forceinline__ void acc_abs(float4& s, const float4 a) {
    s.x += fabsf(a.x); s.y += fabsf(a.y); s.z += fabsf(a.z); s.w += fabsf(a.w);
}

__global__ void __launch_bounds__(THREADS, 2)
k_fused(const float* __restrict__ x1, const float* __restrict__ x2,
        const float* __restrict__ w,  const float* __restrict__ bias,
        float* __restrict__ out) {
    float4* part = (float4*)smem;                       // [dr][arr][grp][quad]
    float*  nrm  = (float*)(part + PART_F4);            // [dr][arr][px]
    float*  f1s  = nrm + NRM_F;                         // [RB][HW]
    float*  f2s  = f1s + RB * HW;

    const int u   = blockIdx.x;          // 0..511
    const int bb  = u >> 6;              // batch
    const int r0  = (u & 63) * RB;       // first owned row
    const int t   = threadIdx.x;
    const int arr  = t >> 8;             // 0: x1, 1: x2
    const int grp  = (t >> 6) & 3;       // 16-channel group
    const int quad = t & 63;             // float4 quad (pixels 4q..4q+3)

    const size_t f4img = (size_t)bb * CH * (HWHW / 4);
    const float4* px = (const float4*)(arr ? x2 : x1) + f4img
                     + (size_t)(grp * 16) * (HWHW / 4) + quad;

    // per-dr validity + row offsets, hoisted out of the load loop
    bool   vld[6];
    size_t roff[6];
#pragma unroll
    for (int dr = 0; dr < 6; ++dr) {
        const int rr = r0 - 1 + dr;
        vld[dr]  = (rr >= 0) && (rr < HW);
        roff[dr] = (size_t)(vld[dr] ? rr : 0) * (HW / 4);
    }

    // ---- norm phase: rows r0-1 .. r0+4, 16 channels each, one long stream ----
    float4 acc[6];
#pragma unroll
    for (int dr = 0; dr < 6; ++dr) acc[dr] = make_float4(0.f, 0.f, 0.f, 0.f);

#pragma unroll
    for (int j = 0; j < 16; ++j) {
#pragma unroll
        for (int dr = 0; dr < 6; ++dr) {
            if (vld[dr])
                acc_abs(acc[dr], px[(size_t)j * (HWHW / 4) + roff[dr]]);
        }
    }
#pragma unroll
    for (int dr = 0; dr < 6; ++dr)
        part[((dr * 2 + arr) * 4 + grp) * 64 + quad] = acc[dr];
    __syncthreads();

    // ---- reduce 4 group-partials -> 6 norm rows x 2 arrays ----
#pragma unroll
    for (int idx = t; idx < 768; idx += THREADS) {   // (dr, arr, quad)
        const int dr = idx >> 7, ar = (idx >> 6) & 1, qq = idx & 63;
        const float4* p = part + ((dr * 2 + ar) * 4) * 64 + qq;
        float4 s = p[0];
#pragma unroll
        for (int k = 1; k < 4; ++k) {
            const float4 a = p[k * 64];
            s.x += a.x; s.y += a.y; s.z += a.z; s.w += a.w;
        }
        ((float4*)(nrm + (dr * 2 + ar) * HW))[qq] = s;
    }
    __syncthreads();

    // ---- conv factors for RB*HW = 1024 pixels ----
    float wv[9];
#pragma unroll
    for (int i = 0; i < 9; ++i) wv[i] = w[i];
    const float bv = bias[0];

#pragma unroll
    for (int idx = t; idx < RB * HW; idx += THREADS) {
        const int rl  = idx >> 8;        // local row 0..3
        const int cc0 = idx & 255;       // pixel col
        float c1 = bv, c2 = bv;
#pragma unroll
        for (int dr = 0; dr < 3; ++dr) { // nrm rows rl+dr (OOR rows hold zeros)
            const float* n1r = nrm + ((rl + dr) * 2 + 0) * HW;
            const float* n2r = nrm + ((rl + dr) * 2 + 1) * HW;
#pragma unroll
            for (int dj = 0; dj < 3; ++dj) {
                const int cc = cc0 + dj - 1;
                if (cc < 0 || cc >= HW) continue;
                const float ww = wv[dr * 3 + dj];
                c1 += ww * n1r[cc];
                c2 += ww * n2r[cc];
            }
        }
        const float rd = 1.0f / (c1 + c2);
        f1s[idx] = c1 * rd;
        f2s[idx] = c2 * rd;
    }
    __syncthreads();

    // ---- blend: re-read owned rows (L2 hits), streaming store ----
    const float4* p1 = (const float4*)x1 + f4img;
    const float4* p2 = (const float4*)x2 + f4img;
    float4*       po = (float4*)out + f4img;
#pragma unroll
    for (int i = 0; i < 32; ++i) {
        const int e   = i * THREADS + t;      // 0..16383
        const int rl  = e >> 12;              // local row
        const int ch  = (e >> 6) & 63;
        const int qq  = e & 63;
        const size_t off = (size_t)ch * (HWHW / 4) + (size_t)(r0 + rl) * (HW / 4) + qq;
        const float4 a  = __ldcs(p1 + off);
        const float4 v  = __ldcs(p2 + off);
        const float4 F1 = ((const float4*)f1s)[rl * 64 + qq];
        const float4 F2 = ((const float4*)f2s)[rl * 64 + qq];
        float4 o;
        o.x = a.x * F1.x + v.x * F2.x;
        o.y = a.y * F1.y + v.y * F2.y;
        o.z = a.z * F1.z + v.z * F2.z;
        o.w = a.w * F1.w + v.w * F2.w;
        __stcs(po + off, o);
    }
}

extern "C" void kernel_launch(void* const* d_in, const int* in_sizes, int n_in,
                              void* d_out, int out_size) {
    const float* x1   = (const float*)d_in[0];
    const float* x2   = (const float*)d_in[1];
    const float* w    = (const float*)d_in[2];
    const float* bias = (const float*)d_in[3];
    float*       out  = (float*)d_out;

    static bool attr_set = false;
    if (!attr_set) {
        cudaFuncSetAttribute(k_fused, cudaFuncAttributeMaxDynamicSharedMemorySize,
                             SMEM_TOTAL);
        attr_set = true;
    }
    k_fused<<<NB * HW / RB, THREADS, SMEM_TOTAL>>>(x1, x2, w, bias, out);
}